// round 16
// baseline (speedup 1.0000x reference)
#include <cuda_runtime.h>
#include <cuda_fp16.h>
#include <math.h>
#include <stdint.h>

#define BB 8
#define SS 1024
#define HH 1024
#define LL 2048
#define MID_M 341
#define MID_N 512
#define WW (HH*HH)

// -------------------- scratch (device globals) ------------------------------
__device__ __align__(128) float g_q_text[BB*SS*HH];
__device__ __align__(128) float g_k_vis [BB*SS*HH];
__device__ __align__(128) float g_v_vis [BB*SS*HH];
__device__ __align__(128) float g_q_vis [BB*SS*HH];
__device__ __align__(128) float g_k_text[BB*SS*HH];
__device__ __align__(128) float g_v_text[BB*SS*HH];
__device__ __align__(128) float g_att   [BB*LL*HH];
__device__ __align__(128) float g_scores[BB*MID_M*MID_N];
__device__ __align__(128) __half g_vis_hi[BB*SS*HH];
__device__ __align__(128) __half g_vis_lo[BB*SS*HH];
__device__ __align__(128) __half g_txt_hi[BB*SS*HH];
__device__ __align__(128) __half g_txt_lo[BB*SS*HH];
__device__ __align__(128) __half g_c1_hi [BB*LL*HH];
__device__ __align__(128) __half g_w_hi  [4*WW];      // Wq, Wk, Wv, Wc2
__device__ __align__(128) __half g_w_lo  [4*WW];
__device__ __align__(128) __half g_qt_hi [BB*SS*HH];
__device__ __align__(128) __half g_qt_lo [BB*SS*HH];
__device__ __align__(128) __half g_kv_hi [BB*SS*HH];
__device__ __align__(128) __half g_kv_lo [BB*SS*HH];
__device__ __align__(128) __half g_att_hi[BB*LL*HH];
__device__ __align__(128) __half g_wc1r_hi[HH*384];
__device__ __align__(128) __half g_sc_hi [BB*MID_M*MID_N];
__device__ __align__(128) __half g_vvT_hi[BB*HH*MID_N];

// ===================== low-level helpers ====================================
__device__ __forceinline__ uint32_t smem_to_u32(const void* p) {
    uint32_t a;
    asm("{ .reg .u64 t; cvta.to.shared.u64 t, %1; cvt.u32.u64 %0, t; }" : "=r"(a) : "l"(p));
    return a;
}
__device__ __forceinline__ void cp_async16(uint32_t saddr, const void* gptr) {
    asm volatile("cp.async.cg.shared.global [%0], [%1], 16;" :: "r"(saddr), "l"(gptr));
}
#define CP_COMMIT() asm volatile("cp.async.commit_group;" ::: "memory")
#define CP_WAIT1()  asm volatile("cp.async.wait_group 1;" ::: "memory")
#define CP_WAIT0()  asm volatile("cp.async.wait_group 0;" ::: "memory")

__device__ __forceinline__ void ldm_x4(uint32_t& r0, uint32_t& r1, uint32_t& r2, uint32_t& r3,
                                       uint32_t addr) {
    asm volatile("ldmatrix.sync.aligned.m8n8.x4.shared.b16 {%0,%1,%2,%3}, [%4];"
                 : "=r"(r0), "=r"(r1), "=r"(r2), "=r"(r3) : "r"(addr));
}
__device__ __forceinline__ void ldm_x2(uint32_t& r0, uint32_t& r1, uint32_t addr) {
    asm volatile("ldmatrix.sync.aligned.m8n8.x2.shared.b16 {%0,%1}, [%2];"
                 : "=r"(r0), "=r"(r1) : "r"(addr));
}
__device__ __forceinline__ void mma16816(float* c, const uint32_t* a, const uint32_t* b) {
    asm volatile("mma.sync.aligned.m16n8k16.row.col.f32.f16.f16.f32 "
                 "{%0,%1,%2,%3}, {%4,%5,%6,%7}, {%8,%9}, {%0,%1,%2,%3};"
                 : "+f"(c[0]), "+f"(c[1]), "+f"(c[2]), "+f"(c[3])
                 : "r"(a[0]), "r"(a[1]), "r"(a[2]), "r"(a[3]), "r"(b[0]), "r"(b[1]));
}
__device__ __forceinline__ void split2(float v, __half& h, __half& l) {
    h = __float2half_rn(v);
    l = __float2half_rn(v - __half2float(h));
}

// ============ GEMM geometry: CTA tile 128x64, 128 threads, 2 CTAs/SM ========
#define STG 49152u
#define MG_SMEM (2 * 49152)

// =================== generic tensor-core GEMM (2-stage, proven) =============
// TERMS: 3 = Ah*Bh + Ah*Bl + Al*Bh ; 1 = Ah*Bh. HALFOUT writes fp16 hi.
template<bool BIAS, bool HALFOUT, bool GUARD, bool RESID, int TERMS>
__global__ __launch_bounds__(128, 2)
void mma_gemm(const __half* __restrict__ Ahi, const __half* __restrict__ Alo, long long sA,
              const __half* __restrict__ Bhi, const __half* __restrict__ Blo, long long sB,
              float* __restrict__ C, long long sC, int ldc,
              const float* __restrict__ bias,
              __half* __restrict__ Chi,
              const float* __restrict__ Rm, long long sR, int ldr,
              int M, int K)
{
    extern __shared__ char smem[];
    const uint32_t sbase = smem_to_u32(smem);
    const int tid = threadIdx.x;
    const int wid = tid >> 5, lane = tid & 31;
    const int m0 = blockIdx.y * 128, n0 = blockIdx.x * 64;
    const int m_w = (wid & 1) * 64;
    const int n_w = (wid >> 1) * 32;
    const int z = blockIdx.z;
    Ahi += z * sA; if (TERMS >= 2) Alo += z * sA;
    Bhi += z * sB; if (TERMS == 3) Blo += z * sB;
    C   += z * sC;
    if (HALFOUT) Chi += z * sC;
    if (RESID)   Rm  += z * sR;

    const int crow = tid >> 3;
    const int cc16 = tid & 7;
    const int nk = K >> 6;

    auto issue_stage = [&](int kc, int s) {
        const int k0 = kc * 64;
        const uint32_t st = sbase + (uint32_t)s * STG;
        #pragma unroll
        for (int p = 0; p < 8; p++) {
            int row = p * 16 + crow;
            uint32_t soff = (uint32_t)(row * 128) + (uint32_t)((cc16 * 16) ^ ((row & 7) << 4));
            int gm = m0 + row;
            if (GUARD) gm = (gm < M) ? gm : (M - 1);
            long long ga = (long long)gm * K + k0 + cc16 * 8;
            cp_async16(st + soff, Ahi + ga);
            if (TERMS >= 2) cp_async16(st + 16384 + soff, Alo + ga);
            if (p < 4) {
                long long gb = (long long)(n0 + row) * K + k0 + cc16 * 8;
                cp_async16(st + 32768 + soff, Bhi + gb);
                if (TERMS == 3) cp_async16(st + 40960 + soff, Blo + gb);
            }
        }
    };

    uint32_t aRow[4], aXor[4];
    #pragma unroll
    for (int mt = 0; mt < 4; mt++) {
        int r = m_w + 16 * mt + (lane & 15);
        aRow[mt] = (uint32_t)(r * 128);
        aXor[mt] = (uint32_t)((r & 7) << 4);
    }
    const uint32_t aCol = (uint32_t)((lane >> 4) * 16);
    uint32_t bRow[4], bXor[4];
    #pragma unroll
    for (int nt = 0; nt < 4; nt++) {
        int r = n_w + 8 * nt + (lane & 7);
        bRow[nt] = (uint32_t)(r * 128);
        bXor[nt] = (uint32_t)((r & 7) << 4);
    }
    const uint32_t bCol = (uint32_t)(((lane >> 3) & 1) * 16);

    float acc[4][4][4];
    #pragma unroll
    for (int mt = 0; mt < 4; mt++)
        #pragma unroll
        for (int nt = 0; nt < 4; nt++)
            #pragma unroll
            for (int q = 0; q < 4; q++) acc[mt][nt][q] = 0.f;

    uint32_t ah[2][4][4], al[2][4][4], bh[2][4][2], bl[2][4][2];

    auto load_frags = [&](int s, int ks, int pb) {
        const uint32_t st = sbase + (uint32_t)s * STG;
        const uint32_t kb = (uint32_t)(ks * 32);
        #pragma unroll
        for (int mt = 0; mt < 4; mt++) {
            uint32_t ad = st + aRow[mt] + ((kb + aCol) ^ aXor[mt]);
            ldm_x4(ah[pb][mt][0], ah[pb][mt][1], ah[pb][mt][2], ah[pb][mt][3], ad);
            if (TERMS >= 2)
                ldm_x4(al[pb][mt][0], al[pb][mt][1], al[pb][mt][2], al[pb][mt][3], ad + 16384);
        }
        #pragma unroll
        for (int nt = 0; nt < 4; nt++) {
            uint32_t bd = st + 32768 + bRow[nt] + ((kb + bCol) ^ bXor[nt]);
            ldm_x2(bh[pb][nt][0], bh[pb][nt][1], bd);
            if (TERMS == 3) ldm_x2(bl[pb][nt][0], bl[pb][nt][1], bd + 8192);
        }
    };
    auto do_mma = [&](int pb) {
        #pragma unroll
        for (int mt = 0; mt < 4; mt++)
            #pragma unroll
            for (int nt = 0; nt < 4; nt++) {
                mma16816(acc[mt][nt], ah[pb][mt], bh[pb][nt]);
                if (TERMS == 3) mma16816(acc[mt][nt], ah[pb][mt], bl[pb][nt]);
                if (TERMS >= 2) mma16816(acc[mt][nt], al[pb][mt], bh[pb][nt]);
            }
    };

    issue_stage(0, 0); CP_COMMIT();
    issue_stage(1, 1); CP_COMMIT();
    for (int kc = 0; kc < nk; kc++) {
        if (kc + 1 < nk) { CP_WAIT1(); } else { CP_WAIT0(); }
        __syncthreads();
        const int s = kc & 1;
        load_frags(s, 0, 0);
        #pragma unroll
        for (int ks = 0; ks < 4; ks++) {
            if (ks < 3) load_frags(s, ks + 1, (ks + 1) & 1);
            do_mma(ks & 1);
        }
        if (kc + 2 < nk) {
            __syncthreads();
            issue_stage(kc + 2, s); CP_COMMIT();
        }
    }

    const int rq = lane >> 2, cq = (lane & 3) * 2;
    #pragma unroll
    for (int mt = 0; mt < 4; mt++) {
        int row0 = m0 + m_w + 16 * mt + rq;
        #pragma unroll
        for (int nt = 0; nt < 4; nt++) {
            int col = n0 + n_w + 8 * nt + cq;
            float b0 = 0.f, b1 = 0.f;
            if (BIAS) { b0 = bias[col]; b1 = bias[col + 1]; }
            #pragma unroll
            for (int rr = 0; rr < 2; rr++) {
                int row = row0 + rr * 8;
                if (GUARD && row >= M) continue;
                float x0 = acc[mt][nt][rr * 2 + 0] + b0;
                float x1 = acc[mt][nt][rr * 2 + 1] + b1;
                if (RESID) {
                    const float* Rp = Rm + (long long)row * ldr + col;
                    x0 += Rp[0]; x1 += Rp[1];
                }
                long long idx = (long long)row * ldc + col;
                *(float2*)(C + idx) = make_float2(x0, x1);
                if (HALFOUT) {
                    *(__half2*)(Chi + idx) =
                        __halves2half2(__float2half_rn(x0), __float2half_rn(x1));
                }
            }
        }
    }
}

// ============ fused QKV projection for BOTH inputs ==========================
__global__ __launch_bounds__(128, 2)
void mma_qkv(const __half* __restrict__ A0h, const __half* __restrict__ A0l,
             const __half* __restrict__ A1h, const __half* __restrict__ A1l,
             const __half* __restrict__ Bhi, const __half* __restrict__ Blo,
             const float* __restrict__ b0p, const float* __restrict__ b1p,
             const float* __restrict__ b2p,
             float* __restrict__ Cq0, float* __restrict__ Ck0, float* __restrict__ Cv0,
             float* __restrict__ Cq1, float* __restrict__ Ck1, float* __restrict__ Cv1,
             __half* __restrict__ C0hi, __half* __restrict__ C0lo,
             __half* __restrict__ C1hi, __half* __restrict__ C1lo)
{
    extern __shared__ char smem[];
    const uint32_t sbase = smem_to_u32(smem);
    const int tid = threadIdx.x;
    const int wid = tid >> 5, lane = tid & 31;
    const int m0 = blockIdx.y * 128, n0 = blockIdx.x * 64;
    const int m_w = (wid & 1) * 64;
    const int n_w = (wid >> 1) * 32;
    const int z = blockIdx.z;
    const int seg = n0 >> 10;
    const int ncol0 = n0 & 1023;
    const bool t3 = (seg < 2);

    if (z == 0 && seg == 0) {
        int lt = blockIdx.y & 7;
        if (lt == 1 || lt == 6 || lt == 7) return;
    }

    const __half* Ahi = z ? A1h : A0h;
    const __half* Alo = z ? A1l : A0l;
    float* C = z ? ((seg == 0) ? Cq1 : (seg == 1) ? Ck1 : Cv1)
                 : ((seg == 0) ? Cq0 : (seg == 1) ? Ck0 : Cv0);
    const float* bias = (seg == 0) ? b0p : (seg == 1) ? b1p : b2p;
    const bool doHalf = (seg == (z ? 1 : 0));
    const bool skipF32 = (z == 0 && seg == 0 && (blockIdx.y & 7) != 0);
    __half* Chi = z ? C1hi : C0hi;
    __half* Clo = z ? C1lo : C0lo;

    const int crow = tid >> 3;
    const int cc16 = tid & 7;

    auto issue_stage = [&](int kc, int s) {
        const int k0 = kc * 64;
        const uint32_t st = sbase + (uint32_t)s * STG;
        #pragma unroll
        for (int p = 0; p < 8; p++) {
            int row = p * 16 + crow;
            uint32_t soff = (uint32_t)(row * 128) + (uint32_t)((cc16 * 16) ^ ((row & 7) << 4));
            long long ga = (long long)(m0 + row) * 1024 + k0 + cc16 * 8;
            cp_async16(st + soff, Ahi + ga);
            if (t3) cp_async16(st + 16384 + soff, Alo + ga);
            if (p < 4) {
                long long gb = (long long)(n0 + row) * 1024 + k0 + cc16 * 8;
                cp_async16(st + 32768 + soff, Bhi + gb);
                if (t3) cp_async16(st + 40960 + soff, Blo + gb);
            }
        }
    };

    uint32_t aRow[4], aXor[4];
    #pragma unroll
    for (int mt = 0; mt < 4; mt++) {
        int r = m_w + 16 * mt + (lane & 15);
        aRow[mt] = (uint32_t)(r * 128);
        aXor[mt] = (uint32_t)((r & 7) << 4);
    }
    const uint32_t aCol = (uint32_t)((lane >> 4) * 16);
    uint32_t bRow[4], bXor[4];
    #pragma unroll
    for (int nt = 0; nt < 4; nt++) {
        int r = n_w + 8 * nt + (lane & 7);
        bRow[nt] = (uint32_t)(r * 128);
        bXor[nt] = (uint32_t)((r & 7) << 4);
    }
    const uint32_t bCol = (uint32_t)(((lane >> 3) & 1) * 16);

    float acc[4][4][4];
    #pragma unroll
    for (int mt = 0; mt < 4; mt++)
        #pragma unroll
        for (int nt = 0; nt < 4; nt++)
            #pragma unroll
            for (int q = 0; q < 4; q++) acc[mt][nt][q] = 0.f;

    uint32_t ah[2][4][4], al[2][4][4], bh[2][4][2], bl[2][4][2];

    auto load_frags = [&](int s, int ks, int pb) {
        const uint32_t st = sbase + (uint32_t)s * STG;
        const uint32_t kb = (uint32_t)(ks * 32);
        #pragma unroll
        for (int mt = 0; mt < 4; mt++) {
            uint32_t ad = st + aRow[mt] + ((kb + aCol) ^ aXor[mt]);
            ldm_x4(ah[pb][mt][0], ah[pb][mt][1], ah[pb][mt][2], ah[pb][mt][3], ad);
            if (t3) ldm_x4(al[pb][mt][0], al[pb][mt][1], al[pb][mt][2], al[pb][mt][3], ad + 16384);
        }
        #pragma unroll
        for (int nt = 0; nt < 4; nt++) {
            uint32_t bd = st + 32768 + bRow[nt] + ((kb + bCol) ^ bXor[nt]);
            ldm_x2(bh[pb][nt][0], bh[pb][nt][1], bd);
            if (t3) ldm_x2(bl[pb][nt][0], bl[pb][nt][1], bd + 8192);
        }
    };
    auto do_mma = [&](int pb) {
        #pragma unroll
        for (int mt = 0; mt < 4; mt++)
            #pragma unroll
            for (int nt = 0; nt < 4; nt++) {
                mma16816(acc[mt][nt], ah[pb][mt], bh[pb][nt]);
                if (t3) {
                    mma16816(acc[mt][nt], ah[pb][mt], bl[pb][nt]);
                    mma16816(acc[mt][nt], al[pb][mt], bh[pb][nt]);
                }
            }
    };

    issue_stage(0, 0); CP_COMMIT();
    issue_stage(1, 1); CP_COMMIT();
    for (int kc = 0; kc < 16; kc++) {
        if (kc + 1 < 16) { CP_WAIT1(); } else { CP_WAIT0(); }
        __syncthreads();
        const int s = kc & 1;
        load_frags(s, 0, 0);
        #pragma unroll
        for (int ks = 0; ks < 4; ks++) {
            if (ks < 3) load_frags(s, ks + 1, (ks + 1) & 1);
            do_mma(ks & 1);
        }
        if (kc + 2 < 16) {
            __syncthreads();
            issue_stage(kc + 2, s); CP_COMMIT();
        }
    }

    const int rq = lane >> 2, cq = (lane & 3) * 2;
    #pragma unroll
    for (int mt = 0; mt < 4; mt++) {
        int row0 = m0 + m_w + 16 * mt + rq;
        #pragma unroll
        for (int nt = 0; nt < 4; nt++) {
            int col = ncol0 + n_w + 8 * nt + cq;
            float b0 = bias[col], b1 = bias[col + 1];
            #pragma unroll
            for (int rr = 0; rr < 2; rr++) {
                int row = row0 + rr * 8;
                float x0 = acc[mt][nt][rr * 2 + 0] + b0;
                float x1 = acc[mt][nt][rr * 2 + 1] + b1;
                long long idx = (long long)row * 1024 + col;
                if (!skipF32) *(float2*)(C + idx) = make_float2(x0, x1);
                if (doHalf) {
                    __half h0, l0h, h1, l1h;
                    split2(x0, h0, l0h); split2(x1, h1, l1h);
                    *(__half2*)(Chi + idx) = __halves2half2(h0, h1);
                    *(__half2*)(Clo + idx) = __halves2half2(l0h, l1h);
                }
            }
        }
    }
}

// ===== conv1 (grouped k=3), 1-term (x hi, w hi), single-shot smem ===========
#define CV_SMEM (33280 + 3*32768)

__global__ __launch_bounds__(256, 1)
void conv1_mma(const __half* __restrict__ xh,
               const __half* __restrict__ wh,
               const float* __restrict__ bias,
               __half* __restrict__ oh)
{
    extern __shared__ char smem[];
    const uint32_t sb = smem_to_u32(smem);
    const int tid = threadIdx.x, wid = tid >> 5, lane = tid & 31;
    const int l0 = blockIdx.x * 128, g = blockIdx.y, b = blockIdx.z;
    const int m_w = (wid & 1) * 64, n_w = (wid >> 1) * 32;
    const uint32_t XH = sb, WH = sb + 33280u;

    for (int t = tid; t < 2080; t += 256) {
        int r = t >> 4, c16 = t & 15;
        int l = l0 - 1 + r;
        uint32_t d = (uint32_t)(r * 256) + (uint32_t)((c16 * 16) ^ ((r & 7) << 4));
        uint4 vh = make_uint4(0u, 0u, 0u, 0u);
        if (l >= 0 && l < LL) {
            long long gidx = ((long long)b * LL + l) * HH + g * 128 + c16 * 8;
            vh = *(const uint4*)(xh + gidx);
        }
        *(uint4*)(smem + d) = vh;
    }
    for (int t = tid; t < 3 * 2048; t += 256) {
        int tap = t >> 11, u = t & 2047;
        int r = u >> 4, c16 = u & 15;
        uint32_t d = (uint32_t)(r * 256) + (uint32_t)((c16 * 16) ^ ((r & 7) << 4));
        long long widx = (long long)(g * 128 + r) * 384 + tap * 128 + c16 * 8;
        *(uint4*)(smem + 33280 + tap * 32768 + d) = *(const uint4*)(wh + widx);
    }
    __syncthreads();

    float acc[4][4][4];
    #pragma unroll
    for (int mt = 0; mt < 4; mt++)
        #pragma unroll
        for (int nt = 0; nt < 4; nt++)
            #pragma unroll
            for (int q = 0; q < 4; q++) acc[mt][nt][q] = 0.f;

    const uint32_t aCol = (uint32_t)((lane >> 4) * 16);
    const uint32_t bCol = (uint32_t)(((lane >> 3) & 1) * 16);

    for (int tap = 0; tap < 3; tap++) {
        #pragma unroll
        for (int ks = 0; ks < 8; ks++) {
            const uint32_t kb = (uint32_t)(ks * 32);
            uint32_t ah[4][4], bh[4][2];
            #pragma unroll
            for (int mt = 0; mt < 4; mt++) {
                int ar = m_w + 16 * mt + (lane & 15) + tap;
                uint32_t ad = XH + (uint32_t)(ar * 256) + ((kb + aCol) ^ (uint32_t)((ar & 7) << 4));
                ldm_x4(ah[mt][0], ah[mt][1], ah[mt][2], ah[mt][3], ad);
            }
            #pragma unroll
            for (int nt = 0; nt < 4; nt++) {
                int br = n_w + 8 * nt + (lane & 7);
                uint32_t bd = WH + (uint32_t)(tap * 32768) + (uint32_t)(br * 256)
                            + ((kb + bCol) ^ (uint32_t)((br & 7) << 4));
                ldm_x2(bh[nt][0], bh[nt][1], bd);
            }
            #pragma unroll
            for (int mt = 0; mt < 4; mt++)
                #pragma unroll
                for (int nt = 0; nt < 4; nt++)
                    mma16816(acc[mt][nt], ah[mt], bh[nt]);
        }
    }

    const int rq = lane >> 2, cq = (lane & 3) * 2;
    #pragma unroll
    for (int mt = 0; mt < 4; mt++) {
        int row0 = l0 + m_w + 16 * mt + rq;
        #pragma unroll
        for (int nt = 0; nt < 4; nt++) {
            int ch = g * 128 + n_w + 8 * nt + cq;
            float b0 = bias[ch], b1 = bias[ch + 1];
            #pragma unroll
            for (int rr = 0; rr < 2; rr++) {
                int row = row0 + rr * 8;
                float x0 = acc[mt][nt][rr * 2 + 0] + b0;
                float x1 = acc[mt][nt][rr * 2 + 1] + b1;
                float y0 = 0.5f * x0 * (1.0f + erff(x0 * 0.70710678118654752f));
                float y1 = 0.5f * x1 * (1.0f + erff(x1 * 0.70710678118654752f));
                long long idx = ((long long)b * LL + row) * HH + ch;
                *(__half2*)(oh + idx) =
                    __halves2half2(__float2half_rn(y0), __float2half_rn(y1));
            }
        }
    }
}

// ===== fused prep: input splits + weight splits + conv1 weight transform ====
#define PREP_N4IN (BB*SS*HH/4)
#define PREP_J1 (2*PREP_N4IN)
#define PREP_J2 (PREP_J1 + WW)
#define PREP_J3 (PREP_J2 + HH*384)
__global__ void prep_all(const float4* __restrict__ vis, const float4* __restrict__ txt,
                         uint2* __restrict__ vish, uint2* __restrict__ visl,
                         uint2* __restrict__ txth, uint2* __restrict__ txtl,
                         uint2* __restrict__ atth4,
                         const float4* __restrict__ wq, const float4* __restrict__ wk,
                         const float4* __restrict__ wv, const float4* __restrict__ wc2,
                         uint2* __restrict__ whi, uint2* __restrict__ wlo,
                         const float* __restrict__ Wc1, __half* __restrict__ wc1h)
{
    long long gid = (long long)blockIdx.x * 256 + threadIdx.x;
    if (gid < PREP_J1) {
        int i = (int)gid;
        bool isTxt = (i >= PREP_N4IN);
        if (isTxt) i -= PREP_N4IN;
        const float4* x = isTxt ? txt : vis;
        uint2* hp = isTxt ? txth : vish;
        uint2* lp = isTxt ? txtl : visl;
        float4 v = x[i];
        __half hx, lx, hy, ly, hz, lz, hw, lw;
        split2(v.x, hx, lx); split2(v.y, hy, ly);
        split2(v.z, hz, lz); split2(v.w, hw, lw);
        __half2 a0 = __halves2half2(hx, hy), a1 = __halves2half2(hz, hw);
        __half2 b0 = __halves2half2(lx, ly), b1 = __halves2half2(lz, lw);
        uint2 oh2, ol2;
        oh2.x = *(uint32_t*)&a0; oh2.y = *(uint32_t*)&a1;
        ol2.x = *(uint32_t*)&b0; ol2.y = *(uint32_t*)&b1;
        hp[i] = oh2; lp[i] = ol2;
        if (isTxt) {
            int b = i >> 18, r = i & 262143;
            atth4[(long long)b * 524288 + 262144 + r] = oh2;
        }
    } else if (gid < PREP_J2) {
        int idx = (int)(gid - PREP_J1);
        int seg = idx >> 18, i = idx & 262143;
        const float4* src = (seg == 0) ? wq : (seg == 1) ? wk : (seg == 2) ? wv : wc2;
        float4 v = src[i];
        __half hx, lx, hy, ly, hz, lz, hw, lw;
        split2(v.x, hx, lx); split2(v.y, hy, ly);
        split2(v.z, hz, lz); split2(v.w, hw, lw);
        __half2 a0 = __halves2half2(hx, hy), a1 = __halves2half2(hz, hw);
        __half2 b0 = __halves2half2(lx, ly), b1 = __halves2half2(lz, lw);
        uint2 oh2, ol2;
        oh2.x = *(uint32_t*)&a0; oh2.y = *(uint32_t*)&a1;
        ol2.x = *(uint32_t*)&b0; ol2.y = *(uint32_t*)&b1;
        whi[idx] = oh2;
        if (seg != 3) wlo[idx] = ol2;
    } else if (gid < PREP_J3) {
        int idx = (int)(gid - PREP_J2);
        int o = idx / 384, k = idx % 384;
        int tap = k >> 7, ic = k & 127;
        wc1h[idx] = __float2half_rn(Wc1[(long long)o * 384 + ic * 3 + tap]);
    }
}

__global__ void transpose_vslice(const float* __restrict__ vv, __half* __restrict__ th)
{
    __shared__ float tile[32][33];
    const int t0 = blockIdx.x * 32, h0 = blockIdx.y * 32, b = blockIdx.z;
    const int tx = threadIdx.x, ty = threadIdx.y;
    #pragma unroll
    for (int y = ty; y < 32; y += 8)
        tile[y][tx] = vv[((long long)b * SS + 256 + t0 + y) * HH + h0 + tx];
    __syncthreads();
    #pragma unroll
    for (int y = ty; y < 32; y += 8) {
        long long o = ((long long)b * HH + h0 + y) * MID_N + t0 + tx;
        th[o] = __float2half_rn(tile[tx][y]);
    }
}

// -------- v2t attention: 4 query rows/block, K fp32 + V fp16 smem, 2 CTA/SM -
#define V2T_SMEM (16*1024*4 + 16*1024*2)   // 96 KB

__global__ __launch_bounds__(128, 2) void v2t_tile(
    const float* __restrict__ qvis, const float* __restrict__ ktext,
    const float* __restrict__ vtext, const float* __restrict__ visf,
    __half* __restrict__ atth)
{
    extern __shared__ char smraw[];
    float*  ks = (float*)smraw;                 // [16][1024] fp32
    __half* vs = (__half*)(smraw + 65536);      // [16][1024] fp16
    const int b = blockIdx.y, i0 = blockIdx.x * 4;
    const int tid = threadIdx.x, w = tid >> 5, lane = tid & 31;
    const int w0 = (i0 < 1016) ? i0 : 1016;

    const float* kb = ktext + (long long)b * SS * HH;
    const float* vb = vtext + (long long)b * SS * HH;
    for (int t = tid; t < 16 * 256; t += 128) {
        int slot = t >> 8, c4 = (t & 255) * 4;
        int row = (slot < 5) ? slot : (w0 + slot - 5);
        row = (row < 1023) ? row : 1023;
        long long base = (long long)row * HH + c4;
        *(float4*)(ks + slot * 1024 + c4) = *(const float4*)(kb + base);
        float4 v4 = *(const float4*)(vb + base);
        *(__half2*)(vs + slot * 1024 + c4)     = __floats2half2_rn(v4.x, v4.y);
        *(__half2*)(vs + slot * 1024 + c4 + 2) = __floats2half2_rn(v4.z, v4.w);
    }
    __syncthreads();

    const int i = i0 + w;                 // warp w owns query row i
    const int s0 = (i < 1016) ? i : 1016;
    const int nk = (i < 5) ? (i + 8) : 13;

    const float* q = qvis + ((long long)b * SS + i) * HH;
    float qr[32];
    #pragma unroll
    for (int c = 0; c < 32; c++) qr[c] = q[c * 32 + lane];

    int sl[13];
    float p[13];
    #pragma unroll
    for (int j = 0; j < 13; j++) {
        int row = (i < 5) ? j : ((j < 5) ? j : (s0 + j - 5));
        int slj = (row < 5) ? row : (5 + row - w0);
        sl[j] = (slj < 15) ? slj : 15;   // clamp: only j >= nk (p[j]==0) exceeds 15
        float s = 0.f;
        if (j < nk) {
            const float* kr = ks + sl[j] * 1024;
            #pragma unroll
            for (int c = 0; c < 32; c++) s += qr[c] * kr[c * 32 + lane];
        }
        #pragma unroll
        for (int off = 16; off; off >>= 1) s += __shfl_xor_sync(0xffffffffu, s, off);
        p[j] = s;
    }

    float mx = -3.4e38f;
    #pragma unroll
    for (int j = 0; j < 13; j++) if (j < nk) mx = fmaxf(mx, p[j]);
    float sum = 0.f;
    #pragma unroll
    for (int j = 0; j < 13; j++) {
        float e = (j < nk) ? expf(p[j] - mx) : 0.f;
        p[j] = e; sum += e;
    }
    const float inv = 1.f / sum;
    #pragma unroll
    for (int j = 0; j < 13; j++) p[j] *= inv;

    const float* vf = visf + ((long long)b * SS + i) * HH;
    long long ob = ((long long)b * LL + i) * HH;
    #pragma unroll 4
    for (int r = 0; r < 32; r++) {
        int h = r * 32 + lane;
        float a = vf[h];
        #pragma unroll
        for (int j = 0; j < 13; j++)
            a += p[j] * __half2float(vs[sl[j] * 1024 + h]);
        atth[ob + h] = __float2half_rn(a);
    }
}

// -------------------- t2v rows 0..4 -----------------------------------------
__global__ __launch_bounds__(256) void t2v_full_rows(
    const float* __restrict__ qtext, const float* __restrict__ kvis,
    const float* __restrict__ vvis, const float* __restrict__ txt,
    __half* __restrict__ atth)
{
    const int r = blockIdx.x, b = blockIdx.y;
    const int tid = threadIdx.x, lane = tid & 31, warp = tid >> 5;
    __shared__ float qs[1024];
    __shared__ float sc[1024];
    __shared__ float red[8];

    const float* q = qtext + ((long long)b * SS + r) * HH;
    for (int h = tid; h < 1024; h += 256) qs[h] = q[h];
    __syncthreads();

    const float* kb = kvis + (long long)b * SS * HH;
    for (int t = warp * 128; t < warp * 128 + 128; t++) {
        const float* kp = kb + (long long)t * HH;
        float p = 0.f;
        #pragma unroll
        for (int c = 0; c < 32; c++) p += qs[c * 32 + lane] * kp[c * 32 + lane];
        #pragma unroll
        for (int off = 16; off; off >>= 1) p += __shfl_xor_sync(0xffffffffu, p, off);
        if (lane == 0) sc[t] = p;
    }
    __syncthreads();

    float m = -3.4e38f;
    for (int t = tid; t < 1024; t += 256) m = fmaxf(m, sc[t]);
    #pragma unroll
    for (int off = 16; off; off >>= 1) m = fmaxf(m, __shfl_xor_sync(0xffffffffu, m, off));
    if (lane == 0) red[warp] = m;
    __syncthreads();
    float mx = red[0];
    #pragma unroll
    for (int k = 1; k < 8; k++) mx = fmaxf(mx, red[k]);

    float s = 0.f;
    for (int t = tid; t < 1024; t += 256) { float e = expf(sc[t] - mx); sc[t] = e; s += e; }
    #pragma unroll
    for (int off = 16; off; off >>= 1) s += __shfl_xor_sync(0xffffffffu, s, off);
    __syncthreads();
    if (lane == 0) red[warp] = s;
    __syncthreads();
    float tot = 0.f;
    #pragma unroll
    for (int k = 0; k < 8; k++) tot += red[k];
    const float inv = 1.f / tot;

    const float* vb = vvis + (long long)b * SS * HH;
    const float* tx = txt + ((long long)b * SS + r) * HH;
    long long ob = ((long long)b * LL + 1024 + r) * HH;
    float accv[4] = {0.f, 0.f, 0.f, 0.f};
    for (int t = 0; t < 1024; t++) {
        float pw = sc[t];
        const float* vr = vb + (long long)t * HH + tid;
        accv[0] += pw * vr[0];
        accv[1] += pw * vr[256];
        accv[2] += pw * vr[512];
        accv[3] += pw * vr[768];
    }
    #pragma unroll
    for (int k = 0; k < 4; k++) {
        int h = tid + k * 256;
        float v = tx[h] + accv[k] * inv;
        atth[ob + h] = __float2half_rn(v);
    }
}

// -------------------- softmax over 512-col rows -> probs (fp16 hi) ----------
__global__ __launch_bounds__(256) void softmax512(const float* __restrict__ S,
                                                  __half* __restrict__ ph)
{
    const float* row = S + (long long)blockIdx.x * 512;
    const int tid = threadIdx.x, lane = tid & 31, warp = tid >> 5;
    __shared__ float red[8];
    float a = row[tid], b2 = row[tid + 256];
    float m = fmaxf(a, b2);
    #pragma unroll
    for (int off = 16; off; off >>= 1) m = fmaxf(m, __shfl_xor_sync(0xffffffffu, m, off));
    if (lane == 0) red[warp] = m;
    __syncthreads();
    float mx = red[0];
    #pragma unroll
    for (int k = 1; k < 8; k++) mx = fmaxf(mx, red[k]);
    float e0 = expf(a - mx), e1 = expf(b2 - mx);
    float s = e0 + e1;
    #pragma unroll
    for (int off = 16; off; off >>= 1) s += __shfl_xor_sync(0xffffffffu, s, off);
    __syncthreads();
    if (lane == 0) red[warp] = s;
    __syncthreads();
    float tot = 0.f;
    #pragma unroll
    for (int k = 0; k < 8; k++) tot += red[k];
    float inv = 1.f / tot;
    long long base = (long long)blockIdx.x * 512;
    ph[base + tid]       = __float2half_rn(e0 * inv);
    ph[base + tid + 256] = __float2half_rn(e1 * inv);
}

// -------------------- launcher ----------------------------------------------
extern "C" void kernel_launch(void* const* d_in, const int* in_sizes, int n_in,
                              void* d_out, int out_size)
{
    (void)in_sizes; (void)n_in; (void)out_size;
    const float* vis = (const float*)d_in[0];
    const float* txt = (const float*)d_in[1];
    const float* Wq  = (const float*)d_in[2];  const float* bq  = (const float*)d_in[3];
    const float* Wk  = (const float*)d_in[4];  const float* bk  = (const float*)d_in[5];
    const float* Wv  = (const float*)d_in[6];  const float* bv  = (const float*)d_in[7];
    const float* Wc1 = (const float*)d_in[8];  const float* bc1 = (const float*)d_in[9];
    const float* Wc2 = (const float*)d_in[10]; const float* bc2 = (const float*)d_in[11];
    float* out = (float*)d_out;

    float *qt, *kv, *vv, *qv, *kt, *vt, *attb, *scb;
    __half *vish, *visl, *txth, *txtl, *c1h, *wh, *wl;
    __half *qth, *qtl, *kvh, *kvl, *atth, *wc1h, *sch, *vvTh;
    cudaGetSymbolAddress((void**)&qt,  g_q_text);
    cudaGetSymbolAddress((void**)&kv,  g_k_vis);
    cudaGetSymbolAddress((void**)&vv,  g_v_vis);
    cudaGetSymbolAddress((void**)&qv,  g_q_vis);
    cudaGetSymbolAddress((void**)&kt,  g_k_text);
    cudaGetSymbolAddress((void**)&vt,  g_v_text);
    cudaGetSymbolAddress((void**)&attb, g_att);
    cudaGetSymbolAddress((void**)&scb, g_scores);
    cudaGetSymbolAddress((void**)&vish, g_vis_hi);
    cudaGetSymbolAddress((void**)&visl, g_vis_lo);
    cudaGetSymbolAddress((void**)&txth, g_txt_hi);
    cudaGetSymbolAddress((void**)&txtl, g_txt_lo);
    cudaGetSymbolAddress((void**)&c1h, g_c1_hi);
    cudaGetSymbolAddress((void**)&wh,  g_w_hi);
    cudaGetSymbolAddress((void**)&wl,  g_w_lo);
    cudaGetSymbolAddress((void**)&qth, g_qt_hi);
    cudaGetSymbolAddress((void**)&qtl, g_qt_lo);
    cudaGetSymbolAddress((void**)&kvh, g_kv_hi);
    cudaGetSymbolAddress((void**)&kvl, g_kv_lo);
    cudaGetSymbolAddress((void**)&atth, g_att_hi);
    cudaGetSymbolAddress((void**)&wc1h, g_wc1r_hi);
    cudaGetSymbolAddress((void**)&sch, g_sc_hi);
    cudaGetSymbolAddress((void**)&vvTh, g_vvT_hi);

    cudaFuncSetAttribute((const void*)&mma_qkv,
                         cudaFuncAttributeMaxDynamicSharedMemorySize, MG_SMEM);
    cudaFuncSetAttribute((const void*)&mma_gemm<false, false, true,  false, 3>,
                         cudaFuncAttributeMaxDynamicSharedMemorySize, MG_SMEM);
    cudaFuncSetAttribute((const void*)&mma_gemm<false, true,  true,  true,  1>,
                         cudaFuncAttributeMaxDynamicSharedMemorySize, MG_SMEM);
    cudaFuncSetAttribute((const void*)&mma_gemm<true,  false, false, false, 1>,
                         cudaFuncAttributeMaxDynamicSharedMemorySize, MG_SMEM);
    cudaFuncSetAttribute((const void*)&conv1_mma,
                         cudaFuncAttributeMaxDynamicSharedMemorySize, CV_SMEM);
    cudaFuncSetAttribute((const void*)&v2t_tile,
                         cudaFuncAttributeMaxDynamicSharedMemorySize, V2T_SMEM);

    const long long SH = (long long)SS * HH;
    const long long LH = (long long)LL * HH;
    const long long SCs = (long long)MID_M * MID_N;

    // 0) fused prep: input splits (+att text-row seed) + weight splits + wc1
    long long prepTot = (long long)PREP_J3;
    prep_all<<<(int)((prepTot + 255) / 256), 256>>>(
        (const float4*)vis, (const float4*)txt,
        (uint2*)vish, (uint2*)visl, (uint2*)txth, (uint2*)txtl, (uint2*)atth,
        (const float4*)Wq, (const float4*)Wk, (const float4*)Wv, (const float4*)Wc2,
        (uint2*)wh, (uint2*)wl, Wc1, wc1h);

    // 1) fused QKV projections (q,k 3-term; v 1-term)
    mma_qkv<<<dim3(48, 64, 2), 128, MG_SMEM>>>(
        txth, txtl, vish, visl, wh, wl, bq, bk, bv,
        qt, kt, vt, qv, kv, vv,
        qth, qtl, kvh, kvl);

    // 1b) transpose V slice (off the critical chain)
    transpose_vslice<<<dim3(MID_N / 32, HH / 32, BB), dim3(32, 8)>>>(vv, vvTh);

    // 2) v2t sparse attention (4 rows/block, 2 CTAs/SM)
    v2t_tile<<<dim3(SS / 4, BB), 128, V2T_SMEM>>>(qv, kt, vt, vis, atth);

    // 3) t2v rows 0..4
    t2v_full_rows<<<dim3(5, BB), 256>>>(qt, kv, vv, txt, atth);

    // 4) t2v mid scores (3-term, 2-stage)
    mma_gemm<false, false, true, false, 3><<<dim3(MID_N / 64, 3, BB), 128, MG_SMEM>>>(
        qth + 341 * HH, qtl + 341 * HH, SH,
        kvh + 256 * HH, kvl + 256 * HH, SH,
        scb, SCs, MID_N, nullptr, nullptr, nullptr, 0, 0, MID_M, HH);

    // 5) softmax -> probs fp16
    softmax512<<<BB * MID_M, 256>>>(scb, sch);

    // 6) AV (1-term) + text residual -> att rows (fp16 hi out)
    mma_gemm<false, true, true, true, 1><<<dim3(HH / 64, 3, BB), 128, MG_SMEM>>>(
        sch, sch, SCs,
        vvTh, vvTh, (long long)HH * MID_N,
        attb + (long long)(1024 + 341) * HH, LH, HH,
        nullptr,
        atth + (long long)(1024 + 341) * HH,
        txt + 341 * HH, SH, HH,
        MID_M, MID_N);

    // 7) conv1 (1-term) + GELU -> c1 fp16
    conv1_mma<<<dim3(LL / 128, 8, BB), 256, CV_SMEM>>>(atth, wc1h, bc1, c1h);

    // 8) conv2 (1-term) -> output
    mma_gemm<true, false, false, false, 1><<<dim3(HH / 64, BB * LL / 128, 1), 128, MG_SMEM>>>(
        c1h, c1h, 0, wh + 3 * WW, wh + 3 * WW, 0,
        out, 0, HH, bc2, nullptr, nullptr, 0, 0, BB * LL, HH);
}

// round 17
// speedup vs baseline: 1.0080x; 1.0080x over previous
#include <cuda_runtime.h>
#include <cuda_fp16.h>
#include <math.h>
#include <stdint.h>

#define BB 8
#define SS 1024
#define HH 1024
#define LL 2048
#define MID_M 341
#define MID_N 512
#define WW (HH*HH)

// -------------------- scratch (device globals) ------------------------------
__device__ __align__(128) float g_q_text[BB*SS*HH];
__device__ __align__(128) float g_k_vis [BB*SS*HH];
__device__ __align__(128) float g_v_vis [BB*SS*HH];
__device__ __align__(128) float g_q_vis [BB*SS*HH];
__device__ __align__(128) float g_k_text[BB*SS*HH];
__device__ __align__(128) float g_v_text[BB*SS*HH];
__device__ __align__(128) float g_att   [BB*LL*HH];
__device__ __align__(128) float g_scores[BB*MID_M*MID_N];
__device__ __align__(128) __half g_vis_hi[BB*SS*HH];
__device__ __align__(128) __half g_vis_lo[BB*SS*HH];
__device__ __align__(128) __half g_txt_hi[BB*SS*HH];
__device__ __align__(128) __half g_txt_lo[BB*SS*HH];
__device__ __align__(128) __half g_c1_hi [BB*LL*HH];
__device__ __align__(128) __half g_w_hi  [4*WW];      // Wq, Wk, Wv, Wc2
__device__ __align__(128) __half g_w_lo  [4*WW];
__device__ __align__(128) __half g_qt_hi [BB*SS*HH];
__device__ __align__(128) __half g_qt_lo [BB*SS*HH];
__device__ __align__(128) __half g_kv_hi [BB*SS*HH];
__device__ __align__(128) __half g_kv_lo [BB*SS*HH];
__device__ __align__(128) __half g_att_hi[BB*LL*HH];
__device__ __align__(128) __half g_wc1r_hi[HH*384];
__device__ __align__(128) __half g_sc_hi [BB*MID_M*MID_N];
__device__ __align__(128) __half g_vvT_hi[BB*HH*MID_N];

// ===================== low-level helpers ====================================
__device__ __forceinline__ uint32_t smem_to_u32(const void* p) {
    uint32_t a;
    asm("{ .reg .u64 t; cvta.to.shared.u64 t, %1; cvt.u32.u64 %0, t; }" : "=r"(a) : "l"(p));
    return a;
}
__device__ __forceinline__ void cp_async16(uint32_t saddr, const void* gptr) {
    asm volatile("cp.async.cg.shared.global [%0], [%1], 16;" :: "r"(saddr), "l"(gptr));
}
#define CP_COMMIT() asm volatile("cp.async.commit_group;" ::: "memory")
#define CP_WAIT1()  asm volatile("cp.async.wait_group 1;" ::: "memory")
#define CP_WAIT0()  asm volatile("cp.async.wait_group 0;" ::: "memory")

__device__ __forceinline__ void ldm_x4(uint32_t& r0, uint32_t& r1, uint32_t& r2, uint32_t& r3,
                                       uint32_t addr) {
    asm volatile("ldmatrix.sync.aligned.m8n8.x4.shared.b16 {%0,%1,%2,%3}, [%4];"
                 : "=r"(r0), "=r"(r1), "=r"(r2), "=r"(r3) : "r"(addr));
}
__device__ __forceinline__ void ldm_x2(uint32_t& r0, uint32_t& r1, uint32_t addr) {
    asm volatile("ldmatrix.sync.aligned.m8n8.x2.shared.b16 {%0,%1}, [%2];"
                 : "=r"(r0), "=r"(r1) : "r"(addr));
}
__device__ __forceinline__ void mma16816(float* c, const uint32_t* a, const uint32_t* b) {
    asm volatile("mma.sync.aligned.m16n8k16.row.col.f32.f16.f16.f32 "
                 "{%0,%1,%2,%3}, {%4,%5,%6,%7}, {%8,%9}, {%0,%1,%2,%3};"
                 : "+f"(c[0]), "+f"(c[1]), "+f"(c[2]), "+f"(c[3])
                 : "r"(a[0]), "r"(a[1]), "r"(a[2]), "r"(a[3]), "r"(b[0]), "r"(b[1]));
}
__device__ __forceinline__ void split2(float v, __half& h, __half& l) {
    h = __float2half_rn(v);
    l = __float2half_rn(v - __half2float(h));
}

// ============ GEMM geometry: CTA tile 128x64, 128 threads, 2 CTAs/SM ========
#define STG 49152u
#define MG_SMEM (2 * 49152)

// =================== generic tensor-core GEMM (2-stage, proven) =============
// TERMS: 3 = Ah*Bh + Ah*Bl + Al*Bh ; 1 = Ah*Bh. HALFOUT writes fp16 hi.
template<bool BIAS, bool HALFOUT, bool GUARD, bool RESID, int TERMS>
__global__ __launch_bounds__(128, 2)
void mma_gemm(const __half* __restrict__ Ahi, const __half* __restrict__ Alo, long long sA,
              const __half* __restrict__ Bhi, const __half* __restrict__ Blo, long long sB,
              float* __restrict__ C, long long sC, int ldc,
              const float* __restrict__ bias,
              __half* __restrict__ Chi,
              const float* __restrict__ Rm, long long sR, int ldr,
              int M, int K)
{
    extern __shared__ char smem[];
    const uint32_t sbase = smem_to_u32(smem);
    const int tid = threadIdx.x;
    const int wid = tid >> 5, lane = tid & 31;
    const int m0 = blockIdx.y * 128, n0 = blockIdx.x * 64;
    const int m_w = (wid & 1) * 64;
    const int n_w = (wid >> 1) * 32;
    const int z = blockIdx.z;
    Ahi += z * sA; if (TERMS >= 2) Alo += z * sA;
    Bhi += z * sB; if (TERMS == 3) Blo += z * sB;
    C   += z * sC;
    if (HALFOUT) Chi += z * sC;
    if (RESID)   Rm  += z * sR;

    const int crow = tid >> 3;
    const int cc16 = tid & 7;
    const int nk = K >> 6;

    auto issue_stage = [&](int kc, int s) {
        const int k0 = kc * 64;
        const uint32_t st = sbase + (uint32_t)s * STG;
        #pragma unroll
        for (int p = 0; p < 8; p++) {
            int row = p * 16 + crow;
            uint32_t soff = (uint32_t)(row * 128) + (uint32_t)((cc16 * 16) ^ ((row & 7) << 4));
            int gm = m0 + row;
            if (GUARD) gm = (gm < M) ? gm : (M - 1);
            long long ga = (long long)gm * K + k0 + cc16 * 8;
            cp_async16(st + soff, Ahi + ga);
            if (TERMS >= 2) cp_async16(st + 16384 + soff, Alo + ga);
            if (p < 4) {
                long long gb = (long long)(n0 + row) * K + k0 + cc16 * 8;
                cp_async16(st + 32768 + soff, Bhi + gb);
                if (TERMS == 3) cp_async16(st + 40960 + soff, Blo + gb);
            }
        }
    };

    uint32_t aRow[4], aXor[4];
    #pragma unroll
    for (int mt = 0; mt < 4; mt++) {
        int r = m_w + 16 * mt + (lane & 15);
        aRow[mt] = (uint32_t)(r * 128);
        aXor[mt] = (uint32_t)((r & 7) << 4);
    }
    const uint32_t aCol = (uint32_t)((lane >> 4) * 16);
    uint32_t bRow[4], bXor[4];
    #pragma unroll
    for (int nt = 0; nt < 4; nt++) {
        int r = n_w + 8 * nt + (lane & 7);
        bRow[nt] = (uint32_t)(r * 128);
        bXor[nt] = (uint32_t)((r & 7) << 4);
    }
    const uint32_t bCol = (uint32_t)(((lane >> 3) & 1) * 16);

    float acc[4][4][4];
    #pragma unroll
    for (int mt = 0; mt < 4; mt++)
        #pragma unroll
        for (int nt = 0; nt < 4; nt++)
            #pragma unroll
            for (int q = 0; q < 4; q++) acc[mt][nt][q] = 0.f;

    uint32_t ah[2][4][4], al[2][4][4], bh[2][4][2], bl[2][4][2];

    auto load_frags = [&](int s, int ks, int pb) {
        const uint32_t st = sbase + (uint32_t)s * STG;
        const uint32_t kb = (uint32_t)(ks * 32);
        #pragma unroll
        for (int mt = 0; mt < 4; mt++) {
            uint32_t ad = st + aRow[mt] + ((kb + aCol) ^ aXor[mt]);
            ldm_x4(ah[pb][mt][0], ah[pb][mt][1], ah[pb][mt][2], ah[pb][mt][3], ad);
            if (TERMS >= 2)
                ldm_x4(al[pb][mt][0], al[pb][mt][1], al[pb][mt][2], al[pb][mt][3], ad + 16384);
        }
        #pragma unroll
        for (int nt = 0; nt < 4; nt++) {
            uint32_t bd = st + 32768 + bRow[nt] + ((kb + bCol) ^ bXor[nt]);
            ldm_x2(bh[pb][nt][0], bh[pb][nt][1], bd);
            if (TERMS == 3) ldm_x2(bl[pb][nt][0], bl[pb][nt][1], bd + 8192);
        }
    };
    auto do_mma = [&](int pb) {
        #pragma unroll
        for (int mt = 0; mt < 4; mt++)
            #pragma unroll
            for (int nt = 0; nt < 4; nt++) {
                mma16816(acc[mt][nt], ah[pb][mt], bh[pb][nt]);
                if (TERMS == 3) mma16816(acc[mt][nt], ah[pb][mt], bl[pb][nt]);
                if (TERMS >= 2) mma16816(acc[mt][nt], al[pb][mt], bh[pb][nt]);
            }
    };

    issue_stage(0, 0); CP_COMMIT();
    issue_stage(1, 1); CP_COMMIT();
    for (int kc = 0; kc < nk; kc++) {
        if (kc + 1 < nk) { CP_WAIT1(); } else { CP_WAIT0(); }
        __syncthreads();
        const int s = kc & 1;
        load_frags(s, 0, 0);
        #pragma unroll
        for (int ks = 0; ks < 4; ks++) {
            if (ks < 3) load_frags(s, ks + 1, (ks + 1) & 1);
            do_mma(ks & 1);
        }
        if (kc + 2 < nk) {
            __syncthreads();
            issue_stage(kc + 2, s); CP_COMMIT();
        }
    }

    const int rq = lane >> 2, cq = (lane & 3) * 2;
    #pragma unroll
    for (int mt = 0; mt < 4; mt++) {
        int row0 = m0 + m_w + 16 * mt + rq;
        #pragma unroll
        for (int nt = 0; nt < 4; nt++) {
            int col = n0 + n_w + 8 * nt + cq;
            float b0 = 0.f, b1 = 0.f;
            if (BIAS) { b0 = bias[col]; b1 = bias[col + 1]; }
            #pragma unroll
            for (int rr = 0; rr < 2; rr++) {
                int row = row0 + rr * 8;
                if (GUARD && row >= M) continue;
                float x0 = acc[mt][nt][rr * 2 + 0] + b0;
                float x1 = acc[mt][nt][rr * 2 + 1] + b1;
                if (RESID) {
                    const float* Rp = Rm + (long long)row * ldr + col;
                    x0 += Rp[0]; x1 += Rp[1];
                }
                long long idx = (long long)row * ldc + col;
                *(float2*)(C + idx) = make_float2(x0, x1);
                if (HALFOUT) {
                    *(__half2*)(Chi + idx) =
                        __halves2half2(__float2half_rn(x0), __float2half_rn(x1));
                }
            }
        }
    }
}

// ============ fused QKV projection for BOTH inputs ==========================
__global__ __launch_bounds__(128, 2)
void mma_qkv(const __half* __restrict__ A0h, const __half* __restrict__ A0l,
             const __half* __restrict__ A1h, const __half* __restrict__ A1l,
             const __half* __restrict__ Bhi, const __half* __restrict__ Blo,
             const float* __restrict__ b0p, const float* __restrict__ b1p,
             const float* __restrict__ b2p,
             float* __restrict__ Cq0, float* __restrict__ Ck0, float* __restrict__ Cv0,
             float* __restrict__ Cq1, float* __restrict__ Ck1, float* __restrict__ Cv1,
             __half* __restrict__ C0hi, __half* __restrict__ C0lo,
             __half* __restrict__ C1hi, __half* __restrict__ C1lo)
{
    extern __shared__ char smem[];
    const uint32_t sbase = smem_to_u32(smem);
    const int tid = threadIdx.x;
    const int wid = tid >> 5, lane = tid & 31;
    const int m0 = blockIdx.y * 128, n0 = blockIdx.x * 64;
    const int m_w = (wid & 1) * 64;
    const int n_w = (wid >> 1) * 32;
    const int z = blockIdx.z;
    const int seg = n0 >> 10;
    const int ncol0 = n0 & 1023;
    const bool t3 = (seg < 2);

    if (z == 0 && seg == 0) {
        int lt = blockIdx.y & 7;
        if (lt == 1 || lt == 6 || lt == 7) return;
    }

    const __half* Ahi = z ? A1h : A0h;
    const __half* Alo = z ? A1l : A0l;
    float* C = z ? ((seg == 0) ? Cq1 : (seg == 1) ? Ck1 : Cv1)
                 : ((seg == 0) ? Cq0 : (seg == 1) ? Ck0 : Cv0);
    const float* bias = (seg == 0) ? b0p : (seg == 1) ? b1p : b2p;
    const bool doHalf = (seg == (z ? 1 : 0));
    const bool skipF32 = (z == 0 && seg == 0 && (blockIdx.y & 7) != 0);
    __half* Chi = z ? C1hi : C0hi;
    __half* Clo = z ? C1lo : C0lo;

    const int crow = tid >> 3;
    const int cc16 = tid & 7;

    auto issue_stage = [&](int kc, int s) {
        const int k0 = kc * 64;
        const uint32_t st = sbase + (uint32_t)s * STG;
        #pragma unroll
        for (int p = 0; p < 8; p++) {
            int row = p * 16 + crow;
            uint32_t soff = (uint32_t)(row * 128) + (uint32_t)((cc16 * 16) ^ ((row & 7) << 4));
            long long ga = (long long)(m0 + row) * 1024 + k0 + cc16 * 8;
            cp_async16(st + soff, Ahi + ga);
            if (t3) cp_async16(st + 16384 + soff, Alo + ga);
            if (p < 4) {
                long long gb = (long long)(n0 + row) * 1024 + k0 + cc16 * 8;
                cp_async16(st + 32768 + soff, Bhi + gb);
                if (t3) cp_async16(st + 40960 + soff, Blo + gb);
            }
        }
    };

    uint32_t aRow[4], aXor[4];
    #pragma unroll
    for (int mt = 0; mt < 4; mt++) {
        int r = m_w + 16 * mt + (lane & 15);
        aRow[mt] = (uint32_t)(r * 128);
        aXor[mt] = (uint32_t)((r & 7) << 4);
    }
    const uint32_t aCol = (uint32_t)((lane >> 4) * 16);
    uint32_t bRow[4], bXor[4];
    #pragma unroll
    for (int nt = 0; nt < 4; nt++) {
        int r = n_w + 8 * nt + (lane & 7);
        bRow[nt] = (uint32_t)(r * 128);
        bXor[nt] = (uint32_t)((r & 7) << 4);
    }
    const uint32_t bCol = (uint32_t)(((lane >> 3) & 1) * 16);

    float acc[4][4][4];
    #pragma unroll
    for (int mt = 0; mt < 4; mt++)
        #pragma unroll
        for (int nt = 0; nt < 4; nt++)
            #pragma unroll
            for (int q = 0; q < 4; q++) acc[mt][nt][q] = 0.f;

    uint32_t ah[2][4][4], al[2][4][4], bh[2][4][2], bl[2][4][2];

    auto load_frags = [&](int s, int ks, int pb) {
        const uint32_t st = sbase + (uint32_t)s * STG;
        const uint32_t kb = (uint32_t)(ks * 32);
        #pragma unroll
        for (int mt = 0; mt < 4; mt++) {
            uint32_t ad = st + aRow[mt] + ((kb + aCol) ^ aXor[mt]);
            ldm_x4(ah[pb][mt][0], ah[pb][mt][1], ah[pb][mt][2], ah[pb][mt][3], ad);
            if (t3) ldm_x4(al[pb][mt][0], al[pb][mt][1], al[pb][mt][2], al[pb][mt][3], ad + 16384);
        }
        #pragma unroll
        for (int nt = 0; nt < 4; nt++) {
            uint32_t bd = st + 32768 + bRow[nt] + ((kb + bCol) ^ bXor[nt]);
            ldm_x2(bh[pb][nt][0], bh[pb][nt][1], bd);
            if (t3) ldm_x2(bl[pb][nt][0], bl[pb][nt][1], bd + 8192);
        }
    };
    auto do_mma = [&](int pb) {
        #pragma unroll
        for (int mt = 0; mt < 4; mt++)
            #pragma unroll
            for (int nt = 0; nt < 4; nt++) {
                mma16816(acc[mt][nt], ah[pb][mt], bh[pb][nt]);
                if (t3) {
                    mma16816(acc[mt][nt], ah[pb][mt], bl[pb][nt]);
                    mma16816(acc[mt][nt], al[pb][mt], bh[pb][nt]);
                }
            }
    };

    issue_stage(0, 0); CP_COMMIT();
    issue_stage(1, 1); CP_COMMIT();
    for (int kc = 0; kc < 16; kc++) {
        if (kc + 1 < 16) { CP_WAIT1(); } else { CP_WAIT0(); }
        __syncthreads();
        const int s = kc & 1;
        load_frags(s, 0, 0);
        #pragma unroll
        for (int ks = 0; ks < 4; ks++) {
            if (ks < 3) load_frags(s, ks + 1, (ks + 1) & 1);
            do_mma(ks & 1);
        }
        if (kc + 2 < 16) {
            __syncthreads();
            issue_stage(kc + 2, s); CP_COMMIT();
        }
    }

    const int rq = lane >> 2, cq = (lane & 3) * 2;
    #pragma unroll
    for (int mt = 0; mt < 4; mt++) {
        int row0 = m0 + m_w + 16 * mt + rq;
        #pragma unroll
        for (int nt = 0; nt < 4; nt++) {
            int col = ncol0 + n_w + 8 * nt + cq;
            float b0 = bias[col], b1 = bias[col + 1];
            #pragma unroll
            for (int rr = 0; rr < 2; rr++) {
                int row = row0 + rr * 8;
                float x0 = acc[mt][nt][rr * 2 + 0] + b0;
                float x1 = acc[mt][nt][rr * 2 + 1] + b1;
                long long idx = (long long)row * 1024 + col;
                if (!skipF32) *(float2*)(C + idx) = make_float2(x0, x1);
                if (doHalf) {
                    __half h0, l0h, h1, l1h;
                    split2(x0, h0, l0h); split2(x1, h1, l1h);
                    *(__half2*)(Chi + idx) = __halves2half2(h0, h1);
                    *(__half2*)(Clo + idx) = __halves2half2(l0h, l1h);
                }
            }
        }
    }
}

// ===== conv1 (grouped k=3), 1-term (x hi, w hi), single-shot smem ===========
#define CV_SMEM (33280 + 3*32768)

__global__ __launch_bounds__(256, 1)
void conv1_mma(const __half* __restrict__ xh,
               const __half* __restrict__ wh,
               const float* __restrict__ bias,
               __half* __restrict__ oh)
{
    extern __shared__ char smem[];
    const uint32_t sb = smem_to_u32(smem);
    const int tid = threadIdx.x, wid = tid >> 5, lane = tid & 31;
    const int l0 = blockIdx.x * 128, g = blockIdx.y, b = blockIdx.z;
    const int m_w = (wid & 1) * 64, n_w = (wid >> 1) * 32;
    const uint32_t XH = sb, WH = sb + 33280u;

    for (int t = tid; t < 2080; t += 256) {
        int r = t >> 4, c16 = t & 15;
        int l = l0 - 1 + r;
        uint32_t d = (uint32_t)(r * 256) + (uint32_t)((c16 * 16) ^ ((r & 7) << 4));
        uint4 vh = make_uint4(0u, 0u, 0u, 0u);
        if (l >= 0 && l < LL) {
            long long gidx = ((long long)b * LL + l) * HH + g * 128 + c16 * 8;
            vh = *(const uint4*)(xh + gidx);
        }
        *(uint4*)(smem + d) = vh;
    }
    for (int t = tid; t < 3 * 2048; t += 256) {
        int tap = t >> 11, u = t & 2047;
        int r = u >> 4, c16 = u & 15;
        uint32_t d = (uint32_t)(r * 256) + (uint32_t)((c16 * 16) ^ ((r & 7) << 4));
        long long widx = (long long)(g * 128 + r) * 384 + tap * 128 + c16 * 8;
        *(uint4*)(smem + 33280 + tap * 32768 + d) = *(const uint4*)(wh + widx);
    }
    __syncthreads();

    float acc[4][4][4];
    #pragma unroll
    for (int mt = 0; mt < 4; mt++)
        #pragma unroll
        for (int nt = 0; nt < 4; nt++)
            #pragma unroll
            for (int q = 0; q < 4; q++) acc[mt][nt][q] = 0.f;

    const uint32_t aCol = (uint32_t)((lane >> 4) * 16);
    const uint32_t bCol = (uint32_t)(((lane >> 3) & 1) * 16);

    for (int tap = 0; tap < 3; tap++) {
        #pragma unroll
        for (int ks = 0; ks < 8; ks++) {
            const uint32_t kb = (uint32_t)(ks * 32);
            uint32_t ah[4][4], bh[4][2];
            #pragma unroll
            for (int mt = 0; mt < 4; mt++) {
                int ar = m_w + 16 * mt + (lane & 15) + tap;
                uint32_t ad = XH + (uint32_t)(ar * 256) + ((kb + aCol) ^ (uint32_t)((ar & 7) << 4));
                ldm_x4(ah[mt][0], ah[mt][1], ah[mt][2], ah[mt][3], ad);
            }
            #pragma unroll
            for (int nt = 0; nt < 4; nt++) {
                int br = n_w + 8 * nt + (lane & 7);
                uint32_t bd = WH + (uint32_t)(tap * 32768) + (uint32_t)(br * 256)
                            + ((kb + bCol) ^ (uint32_t)((br & 7) << 4));
                ldm_x2(bh[nt][0], bh[nt][1], bd);
            }
            #pragma unroll
            for (int mt = 0; mt < 4; mt++)
                #pragma unroll
                for (int nt = 0; nt < 4; nt++)
                    mma16816(acc[mt][nt], ah[mt], bh[nt]);
        }
    }

    const int rq = lane >> 2, cq = (lane & 3) * 2;
    #pragma unroll
    for (int mt = 0; mt < 4; mt++) {
        int row0 = l0 + m_w + 16 * mt + rq;
        #pragma unroll
        for (int nt = 0; nt < 4; nt++) {
            int ch = g * 128 + n_w + 8 * nt + cq;
            float b0 = bias[ch], b1 = bias[ch + 1];
            #pragma unroll
            for (int rr = 0; rr < 2; rr++) {
                int row = row0 + rr * 8;
                float x0 = acc[mt][nt][rr * 2 + 0] + b0;
                float x1 = acc[mt][nt][rr * 2 + 1] + b1;
                float y0 = 0.5f * x0 * (1.0f + erff(x0 * 0.70710678118654752f));
                float y1 = 0.5f * x1 * (1.0f + erff(x1 * 0.70710678118654752f));
                long long idx = ((long long)b * LL + row) * HH + ch;
                *(__half2*)(oh + idx) =
                    __halves2half2(__float2half_rn(y0), __float2half_rn(y1));
            }
        }
    }
}

// ===== fused prep: input splits + weight splits + conv1 weight transform ====
#define PREP_N4IN (BB*SS*HH/4)
#define PREP_J1 (2*PREP_N4IN)
#define PREP_J2 (PREP_J1 + WW)
#define PREP_J3 (PREP_J2 + HH*384)
__global__ void prep_all(const float4* __restrict__ vis, const float4* __restrict__ txt,
                         uint2* __restrict__ vish, uint2* __restrict__ visl,
                         uint2* __restrict__ txth, uint2* __restrict__ txtl,
                         uint2* __restrict__ atth4,
                         const float4* __restrict__ wq, const float4* __restrict__ wk,
                         const float4* __restrict__ wv, const float4* __restrict__ wc2,
                         uint2* __restrict__ whi, uint2* __restrict__ wlo,
                         const float* __restrict__ Wc1, __half* __restrict__ wc1h)
{
    long long gid = (long long)blockIdx.x * 256 + threadIdx.x;
    if (gid < PREP_J1) {
        int i = (int)gid;
        bool isTxt = (i >= PREP_N4IN);
        if (isTxt) i -= PREP_N4IN;
        const float4* x = isTxt ? txt : vis;
        uint2* hp = isTxt ? txth : vish;
        uint2* lp = isTxt ? txtl : visl;
        float4 v = x[i];
        __half hx, lx, hy, ly, hz, lz, hw, lw;
        split2(v.x, hx, lx); split2(v.y, hy, ly);
        split2(v.z, hz, lz); split2(v.w, hw, lw);
        __half2 a0 = __halves2half2(hx, hy), a1 = __halves2half2(hz, hw);
        __half2 b0 = __halves2half2(lx, ly), b1 = __halves2half2(lz, lw);
        uint2 oh2, ol2;
        oh2.x = *(uint32_t*)&a0; oh2.y = *(uint32_t*)&a1;
        ol2.x = *(uint32_t*)&b0; ol2.y = *(uint32_t*)&b1;
        hp[i] = oh2; lp[i] = ol2;
        if (isTxt) {
            int b = i >> 18, r = i & 262143;
            atth4[(long long)b * 524288 + 262144 + r] = oh2;
        }
    } else if (gid < PREP_J2) {
        int idx = (int)(gid - PREP_J1);
        int seg = idx >> 18, i = idx & 262143;
        const float4* src = (seg == 0) ? wq : (seg == 1) ? wk : (seg == 2) ? wv : wc2;
        float4 v = src[i];
        __half hx, lx, hy, ly, hz, lz, hw, lw;
        split2(v.x, hx, lx); split2(v.y, hy, ly);
        split2(v.z, hz, lz); split2(v.w, hw, lw);
        __half2 a0 = __halves2half2(hx, hy), a1 = __halves2half2(hz, hw);
        __half2 b0 = __halves2half2(lx, ly), b1 = __halves2half2(lz, lw);
        uint2 oh2, ol2;
        oh2.x = *(uint32_t*)&a0; oh2.y = *(uint32_t*)&a1;
        ol2.x = *(uint32_t*)&b0; ol2.y = *(uint32_t*)&b1;
        whi[idx] = oh2;
        if (seg != 3) wlo[idx] = ol2;
    } else if (gid < PREP_J3) {
        int idx = (int)(gid - PREP_J2);
        int o = idx / 384, k = idx % 384;
        int tap = k >> 7, ic = k & 127;
        wc1h[idx] = __float2half_rn(Wc1[(long long)o * 384 + ic * 3 + tap]);
    }
}

__global__ void transpose_vslice(const float* __restrict__ vv, __half* __restrict__ th)
{
    __shared__ float tile[32][33];
    const int t0 = blockIdx.x * 32, h0 = blockIdx.y * 32, b = blockIdx.z;
    const int tx = threadIdx.x, ty = threadIdx.y;
    #pragma unroll
    for (int y = ty; y < 32; y += 8)
        tile[y][tx] = vv[((long long)b * SS + 256 + t0 + y) * HH + h0 + tx];
    __syncthreads();
    #pragma unroll
    for (int y = ty; y < 32; y += 8) {
        long long o = ((long long)b * HH + h0 + y) * MID_N + t0 + tx;
        th[o] = __float2half_rn(tile[tx][y]);
    }
}

// -------- v2t attention: 4 query rows/block, K fp32 + V fp16 smem, 2 CTA/SM -
#define V2T_SMEM (16*1024*4 + 16*1024*2)   // 96 KB

__global__ __launch_bounds__(128, 2) void v2t_tile(
    const float* __restrict__ qvis, const float* __restrict__ ktext,
    const float* __restrict__ vtext, const float* __restrict__ visf,
    __half* __restrict__ atth)
{
    extern __shared__ char smraw[];
    float*  ks = (float*)smraw;                 // [16][1024] fp32
    __half* vs = (__half*)(smraw + 65536);      // [16][1024] fp16
    const int b = blockIdx.y, i0 = blockIdx.x * 4;
    const int tid = threadIdx.x, w = tid >> 5, lane = tid & 31;
    const int w0 = (i0 < 1016) ? i0 : 1016;

    const float* kb = ktext + (long long)b * SS * HH;
    const float* vb = vtext + (long long)b * SS * HH;
    for (int t = tid; t < 16 * 256; t += 128) {
        int slot = t >> 8, c4 = (t & 255) * 4;
        int row = (slot < 5) ? slot : (w0 + slot - 5);
        row = (row < 1023) ? row : 1023;
        long long base = (long long)row * HH + c4;
        *(float4*)(ks + slot * 1024 + c4) = *(const float4*)(kb + base);
        float4 v4 = *(const float4*)(vb + base);
        *(__half2*)(vs + slot * 1024 + c4)     = __floats2half2_rn(v4.x, v4.y);
        *(__half2*)(vs + slot * 1024 + c4 + 2) = __floats2half2_rn(v4.z, v4.w);
    }
    __syncthreads();

    const int i = i0 + w;                 // warp w owns query row i
    const int s0 = (i < 1016) ? i : 1016;
    const int nk = (i < 5) ? (i + 8) : 13;

    const float* q = qvis + ((long long)b * SS + i) * HH;
    float qr[32];
    #pragma unroll
    for (int c = 0; c < 32; c++) qr[c] = q[c * 32 + lane];

    int sl[13];
    float p[13];
    #pragma unroll
    for (int j = 0; j < 13; j++) {
        int row = (i < 5) ? j : ((j < 5) ? j : (s0 + j - 5));
        int slj = (row < 5) ? row : (5 + row - w0);
        sl[j] = (slj < 15) ? slj : 15;   // clamp: only j >= nk (p[j]==0) exceeds 15
        float s = 0.f;
        if (j < nk) {
            const float* kr = ks + sl[j] * 1024;
            #pragma unroll
            for (int c = 0; c < 32; c++) s += qr[c] * kr[c * 32 + lane];
        }
        #pragma unroll
        for (int off = 16; off; off >>= 1) s += __shfl_xor_sync(0xffffffffu, s, off);
        p[j] = s;
    }

    float mx = -3.4e38f;
    #pragma unroll
    for (int j = 0; j < 13; j++) if (j < nk) mx = fmaxf(mx, p[j]);
    float sum = 0.f;
    #pragma unroll
    for (int j = 0; j < 13; j++) {
        float e = (j < nk) ? expf(p[j] - mx) : 0.f;
        p[j] = e; sum += e;
    }
    const float inv = 1.f / sum;
    #pragma unroll
    for (int j = 0; j < 13; j++) p[j] *= inv;

    const float* vf = visf + ((long long)b * SS + i) * HH;
    long long ob = ((long long)b * LL + i) * HH;
    #pragma unroll 4
    for (int r = 0; r < 32; r++) {
        int h = r * 32 + lane;
        float a = vf[h];
        #pragma unroll
        for (int j = 0; j < 13; j++)
            a += p[j] * __half2float(vs[sl[j] * 1024 + h]);
        atth[ob + h] = __float2half_rn(a);
    }
}

// --------- t2v rows 0..4, parallel over 4 h-chunks (grid 5 x 4 x B) ---------
__global__ __launch_bounds__(256) void t2v_full_rows(
    const float* __restrict__ qtext, const float* __restrict__ kvis,
    const float* __restrict__ vvis, const float* __restrict__ txt,
    __half* __restrict__ atth)
{
    const int r = blockIdx.x, hc = blockIdx.y, b = blockIdx.z;
    const int tid = threadIdx.x, lane = tid & 31, warp = tid >> 5;
    __shared__ float qs[1024];
    __shared__ float sc[1024];
    __shared__ float red[8];

    const float* q = qtext + ((long long)b * SS + r) * HH;
    for (int h = tid; h < 1024; h += 256) qs[h] = q[h];
    __syncthreads();

    const float* kb = kvis + (long long)b * SS * HH;
    for (int t = warp * 128; t < warp * 128 + 128; t++) {
        const float* kp = kb + (long long)t * HH;
        float p = 0.f;
        #pragma unroll
        for (int c = 0; c < 32; c++) p += qs[c * 32 + lane] * kp[c * 32 + lane];
        #pragma unroll
        for (int off = 16; off; off >>= 1) p += __shfl_xor_sync(0xffffffffu, p, off);
        if (lane == 0) sc[t] = p;
    }
    __syncthreads();

    float m = -3.4e38f;
    for (int t = tid; t < 1024; t += 256) m = fmaxf(m, sc[t]);
    #pragma unroll
    for (int off = 16; off; off >>= 1) m = fmaxf(m, __shfl_xor_sync(0xffffffffu, m, off));
    if (lane == 0) red[warp] = m;
    __syncthreads();
    float mx = red[0];
    #pragma unroll
    for (int k = 1; k < 8; k++) mx = fmaxf(mx, red[k]);

    float s = 0.f;
    for (int t = tid; t < 1024; t += 256) { float e = expf(sc[t] - mx); sc[t] = e; s += e; }
    #pragma unroll
    for (int off = 16; off; off >>= 1) s += __shfl_xor_sync(0xffffffffu, s, off);
    __syncthreads();
    if (lane == 0) red[warp] = s;
    __syncthreads();
    float tot = 0.f;
    #pragma unroll
    for (int k = 0; k < 8; k++) tot += red[k];
    const float inv = 1.f / tot;

    // AV over this block's 256-column chunk; thread tid owns column h.
    const int h = hc * 256 + tid;
    const float* vb = vvis + (long long)b * SS * HH + h;
    float accv = 0.f;
    #pragma unroll 4
    for (int t = 0; t < 1024; t++)
        accv += sc[t] * vb[(long long)t * HH];

    const float* tx = txt + ((long long)b * SS + r) * HH;
    long long ob = ((long long)b * LL + 1024 + r) * HH;
    float v = tx[h] + accv * inv;
    atth[ob + h] = __float2half_rn(v);
}

// -------------------- softmax over 512-col rows -> probs (fp16 hi) ----------
__global__ __launch_bounds__(256) void softmax512(const float* __restrict__ S,
                                                  __half* __restrict__ ph)
{
    const float* row = S + (long long)blockIdx.x * 512;
    const int tid = threadIdx.x, lane = tid & 31, warp = tid >> 5;
    __shared__ float red[8];
    float a = row[tid], b2 = row[tid + 256];
    float m = fmaxf(a, b2);
    #pragma unroll
    for (int off = 16; off; off >>= 1) m = fmaxf(m, __shfl_xor_sync(0xffffffffu, m, off));
    if (lane == 0) red[warp] = m;
    __syncthreads();
    float mx = red[0];
    #pragma unroll
    for (int k = 1; k < 8; k++) mx = fmaxf(mx, red[k]);
    float e0 = expf(a - mx), e1 = expf(b2 - mx);
    float s = e0 + e1;
    #pragma unroll
    for (int off = 16; off; off >>= 1) s += __shfl_xor_sync(0xffffffffu, s, off);
    __syncthreads();
    if (lane == 0) red[warp] = s;
    __syncthreads();
    float tot = 0.f;
    #pragma unroll
    for (int k = 0; k < 8; k++) tot += red[k];
    float inv = 1.f / tot;
    long long base = (long long)blockIdx.x * 512;
    ph[base + tid]       = __float2half_rn(e0 * inv);
    ph[base + tid + 256] = __float2half_rn(e1 * inv);
}

// -------------------- launcher ----------------------------------------------
extern "C" void kernel_launch(void* const* d_in, const int* in_sizes, int n_in,
                              void* d_out, int out_size)
{
    (void)in_sizes; (void)n_in; (void)out_size;
    const float* vis = (const float*)d_in[0];
    const float* txt = (const float*)d_in[1];
    const float* Wq  = (const float*)d_in[2];  const float* bq  = (const float*)d_in[3];
    const float* Wk  = (const float*)d_in[4];  const float* bk  = (const float*)d_in[5];
    const float* Wv  = (const float*)d_in[6];  const float* bv  = (const float*)d_in[7];
    const float* Wc1 = (const float*)d_in[8];  const float* bc1 = (const float*)d_in[9];
    const float* Wc2 = (const float*)d_in[10]; const float* bc2 = (const float*)d_in[11];
    float* out = (float*)d_out;

    float *qt, *kv, *vv, *qv, *kt, *vt, *attb, *scb;
    __half *vish, *visl, *txth, *txtl, *c1h, *wh, *wl;
    __half *qth, *qtl, *kvh, *kvl, *atth, *wc1h, *sch, *vvTh;
    cudaGetSymbolAddress((void**)&qt,  g_q_text);
    cudaGetSymbolAddress((void**)&kv,  g_k_vis);
    cudaGetSymbolAddress((void**)&vv,  g_v_vis);
    cudaGetSymbolAddress((void**)&qv,  g_q_vis);
    cudaGetSymbolAddress((void**)&kt,  g_k_text);
    cudaGetSymbolAddress((void**)&vt,  g_v_text);
    cudaGetSymbolAddress((void**)&attb, g_att);
    cudaGetSymbolAddress((void**)&scb, g_scores);
    cudaGetSymbolAddress((void**)&vish, g_vis_hi);
    cudaGetSymbolAddress((void**)&visl, g_vis_lo);
    cudaGetSymbolAddress((void**)&txth, g_txt_hi);
    cudaGetSymbolAddress((void**)&txtl, g_txt_lo);
    cudaGetSymbolAddress((void**)&c1h, g_c1_hi);
    cudaGetSymbolAddress((void**)&wh,  g_w_hi);
    cudaGetSymbolAddress((void**)&wl,  g_w_lo);
    cudaGetSymbolAddress((void**)&qth, g_qt_hi);
    cudaGetSymbolAddress((void**)&qtl, g_qt_lo);
    cudaGetSymbolAddress((void**)&kvh, g_kv_hi);
    cudaGetSymbolAddress((void**)&kvl, g_kv_lo);
    cudaGetSymbolAddress((void**)&atth, g_att_hi);
    cudaGetSymbolAddress((void**)&wc1h, g_wc1r_hi);
    cudaGetSymbolAddress((void**)&sch, g_sc_hi);
    cudaGetSymbolAddress((void**)&vvTh, g_vvT_hi);

    cudaFuncSetAttribute((const void*)&mma_qkv,
                         cudaFuncAttributeMaxDynamicSharedMemorySize, MG_SMEM);
    cudaFuncSetAttribute((const void*)&mma_gemm<false, false, true,  false, 3>,
                         cudaFuncAttributeMaxDynamicSharedMemorySize, MG_SMEM);
    cudaFuncSetAttribute((const void*)&mma_gemm<false, true,  true,  true,  1>,
                         cudaFuncAttributeMaxDynamicSharedMemorySize, MG_SMEM);
    cudaFuncSetAttribute((const void*)&mma_gemm<true,  false, false, false, 1>,
                         cudaFuncAttributeMaxDynamicSharedMemorySize, MG_SMEM);
    cudaFuncSetAttribute((const void*)&conv1_mma,
                         cudaFuncAttributeMaxDynamicSharedMemorySize, CV_SMEM);
    cudaFuncSetAttribute((const void*)&v2t_tile,
                         cudaFuncAttributeMaxDynamicSharedMemorySize, V2T_SMEM);

    const long long SH = (long long)SS * HH;
    const long long LH = (long long)LL * HH;
    const long long SCs = (long long)MID_M * MID_N;

    // 0) fused prep: input splits (+att text-row seed) + weight splits + wc1
    long long prepTot = (long long)PREP_J3;
    prep_all<<<(int)((prepTot + 255) / 256), 256>>>(
        (const float4*)vis, (const float4*)txt,
        (uint2*)vish, (uint2*)visl, (uint2*)txth, (uint2*)txtl, (uint2*)atth,
        (const float4*)Wq, (const float4*)Wk, (const float4*)Wv, (const float4*)Wc2,
        (uint2*)wh, (uint2*)wl, Wc1, wc1h);

    // 1) fused QKV projections (q,k 3-term; v 1-term)
    mma_qkv<<<dim3(48, 64, 2), 128, MG_SMEM>>>(
        txth, txtl, vish, visl, wh, wl, bq, bk, bv,
        qt, kt, vt, qv, kv, vv,
        qth, qtl, kvh, kvl);

    // 1b) transpose V slice (off the critical chain)
    transpose_vslice<<<dim3(MID_N / 32, HH / 32, BB), dim3(32, 8)>>>(vv, vvTh);

    // 2) v2t sparse attention (4 rows/block, 2 CTAs/SM)
    v2t_tile<<<dim3(SS / 4, BB), 128, V2T_SMEM>>>(qv, kt, vt, vis, atth);

    // 3) t2v rows 0..4 (parallel over 4 h-chunks -> 160 blocks)
    t2v_full_rows<<<dim3(5, 4, BB), 256>>>(qt, kv, vv, txt, atth);

    // 4) t2v mid scores (3-term, 2-stage)
    mma_gemm<false, false, true, false, 3><<<dim3(MID_N / 64, 3, BB), 128, MG_SMEM>>>(
        qth + 341 * HH, qtl + 341 * HH, SH,
        kvh + 256 * HH, kvl + 256 * HH, SH,
        scb, SCs, MID_N, nullptr, nullptr, nullptr, 0, 0, MID_M, HH);

    // 5) softmax -> probs fp16
    softmax512<<<BB * MID_M, 256>>>(scb, sch);

    // 6) AV (1-term) + text residual -> att rows (fp16 hi out)
    mma_gemm<false, true, true, true, 1><<<dim3(HH / 64, 3, BB), 128, MG_SMEM>>>(
        sch, sch, SCs,
        vvTh, vvTh, (long long)HH * MID_N,
        attb + (long long)(1024 + 341) * HH, LH, HH,
        nullptr,
        atth + (long long)(1024 + 341) * HH,
        txt + 341 * HH, SH, HH,
        MID_M, MID_N);

    // 7) conv1 (1-term) + GELU -> c1 fp16
    conv1_mma<<<dim3(LL / 128, 8, BB), 256, CV_SMEM>>>(atth, wc1h, bc1, c1h);

    // 8) conv2 (1-term) -> output
    mma_gemm<true, false, false, false, 1><<<dim3(HH / 64, BB * LL / 128, 1), 128, MG_SMEM>>>(
        c1h, c1h, 0, wh + 3 * WW, wh + 3 * WW, 0,
        out, 0, HH, bc2, nullptr, nullptr, 0, 0, BB * LL, HH);
}